// round 14
// baseline (speedup 1.0000x reference)
#include <cuda_runtime.h>
#include <cuda_bf16.h>
#include <math.h>
#include <float.h>
#include <stdint.h>

// ---------------------------------------------------------------------------
// Problem constants
// ---------------------------------------------------------------------------
#define NS   4096        // samples
#define IND  768         // input dim
#define DD   256         // prototype dim
#define PP   64          // prototypes
#define PPOS 32          // P/2

// ---------------------------------------------------------------------------
// Device scratch (static — no runtime allocation allowed)
// ---------------------------------------------------------------------------
__device__ float          g_dot[NS * PP];        // z·proto dots (1 MB, atomic acc)
__device__ float          g_zn2[NS];             // per-sample ||z||^2
__device__ __nv_bfloat16  g_xhi[NS * IND];       // x hi bf16, [M][K]
__device__ __nv_bfloat16  g_xlo[NS * IND];       // x lo bf16
__device__ __nv_bfloat16  g_bhi[DD * IND];       // W^T hi, [N][K]
__device__ __nv_bfloat16  g_blo[DD * IND];       // W^T lo
__device__ __nv_bfloat16  g_phi[PP * DD];        // proto hi bf16, [P][D]
__device__ __nv_bfloat16  g_plo[PP * DD];        // proto lo bf16
__device__ float          g_pnorm2[PP];
__device__ float          g_pnorm_inv[PP];
__device__ float          g_pp_part[PP];
__device__ unsigned int   g_minBits[PP];
__device__ float          g_pz_sum;
__device__ float          g_cl_sum;
__device__ int            g_num_cnt;

__device__ __forceinline__ float warpSum(float v) {
#pragma unroll
    for (int o = 16; o; o >>= 1) v += __shfl_xor_sync(0xffffffffu, v, o);
    return v;
}

__device__ __forceinline__ uint32_t smem_u32(const void* p) {
    uint32_t a;
    asm("{ .reg .u64 t; cvta.to.shared.u64 t, %1; cvt.u32.u64 %0, t; }"
        : "=r"(a) : "l"(p));
    return a;
}

__device__ __forceinline__ void cp16(uint32_t sdst, const void* gsrc) {
    asm volatile("cp.async.cg.shared.global [%0], [%1], 16;"
                 :: "r"(sdst), "l"(gsrc) : "memory");
}

// m16n8k16 row.col f32.bf16.bf16.f32
__device__ __forceinline__ void mma16816(float (&d)[4], const uint32_t (&a)[4],
                                         const uint32_t (&b)[2]) {
    asm volatile(
        "mma.sync.aligned.m16n8k16.row.col.f32.bf16.bf16.f32 "
        "{%0,%1,%2,%3}, {%4,%5,%6,%7}, {%8,%9}, {%0,%1,%2,%3};"
        : "+f"(d[0]), "+f"(d[1]), "+f"(d[2]), "+f"(d[3])
        : "r"(a[0]), "r"(a[1]), "r"(a[2]), "r"(a[3]),
          "r"(b[0]), "r"(b[1]));
}

__device__ __forceinline__ void ldmx4(uint32_t (&r)[4], uint32_t addr) {
    asm volatile("ldmatrix.sync.aligned.m8n8.x4.shared.b16 {%0,%1,%2,%3}, [%4];"
                 : "=r"(r[0]), "=r"(r[1]), "=r"(r[2]), "=r"(r[3]) : "r"(addr));
}

__device__ __forceinline__ uint32_t bfpack(float a, float b) {
    const __nv_bfloat16 ha = __float2bfloat16_rn(a);
    const __nv_bfloat16 hb = __float2bfloat16_rn(b);
    return ((uint32_t)__bfloat16_as_ushort(hb) << 16) | __bfloat16_as_ushort(ha);
}

// GEMM smem layout (bf16, padded stride 72 bf16 = 144 B), CTA tile 128x64
#define ASTR     72
#define OFF_AHI  0
#define OFF_ALO  18432            // 128*72*2
#define OFF_BHI  36864
#define OFF_BLO  46080            // +64*72*2
#define GBUF     55296
#define SMEM_GEMM (2 * GBUF + 512)   // + zn2s[128]

#define NPROTO   PP                      // 64 proto blocks
#define NCONVW   ((IND / 32) * (DD / 32))// 192 convW blocks

// ---------------------------------------------------------------------------
// K_prep: blocks [0,64) proto norms + pp partials + proto hi/lo split;
//         blocks [64,256) W hi/lo split + transpose. Slow blocks first.
// ---------------------------------------------------------------------------
__global__ __launch_bounds__(256)
void k_prep(const float* __restrict__ proto, const float* __restrict__ W) {
    const int bid = blockIdx.x;
    const int t   = threadIdx.x;

    if (bid < NPROTO) {
        const int i = bid;
        __shared__ float pi[DD];
        __shared__ float red[8];
        __shared__ float ddist[PP];

        float v = proto[i * DD + t];
        pi[t] = v;
        const __nv_bfloat16 h = __float2bfloat16_rn(v);
        g_phi[i * DD + t] = h;
        g_plo[i * DD + t] = __float2bfloat16_rn(v - __bfloat162float(h));

        float nrm = warpSum(v * v);
        if ((t & 31) == 0) red[t >> 5] = nrm;
        __syncthreads();
        if (t == 0) {
            float s = 0.f;
#pragma unroll
            for (int w = 0; w < 8; w++) s += red[w];
            g_pnorm2[i]    = s;
            g_pnorm_inv[i] = 1.0f / fmaxf(sqrtf(s), 1e-8f);
        }
        __syncthreads();

        const int j = t >> 2;
        const int q = t & 3;
        const float* pj = proto + j * DD + q * 64;
        float s = 0.f;
#pragma unroll 8
        for (int d = 0; d < 64; d++) {
            float df = pi[q * 64 + d] - pj[d];
            s += df * df;
        }
        s += __shfl_down_sync(0xffffffffu, s, 1);
        s += __shfl_down_sync(0xffffffffu, s, 2);
        if (q == 0) ddist[j] = (j == i) ? 0.f : sqrtf(fmaxf(s, 0.f));
        __syncthreads();
        if (t == 0) {
            float acc = 0.f;
#pragma unroll
            for (int k = 0; k < PP; k++) acc += ddist[k];
            g_pp_part[i] = acc;
        }
        return;
    }

    // ---- convW: smem-tiled transpose + hi/lo split ----
    {
        __shared__ float tile[32][33];
        const int bid2 = bid - NPROTO;
        const int k0 = (bid2 % (IND / 32)) * 32;
        const int n0 = (bid2 / (IND / 32)) * 32;
        const int tx = t & 31;
        const int ty = t >> 5;

#pragma unroll
        for (int r = 0; r < 4; r++) {
            const int k = ty + r * 8;
            tile[k][tx] = W[(size_t)(k0 + k) * DD + n0 + tx];
        }
        __syncthreads();

#pragma unroll
        for (int r = 0; r < 4; r++) {
            const int n = ty + r * 8;
            const float w = tile[tx][n];
            const __nv_bfloat16 h = __float2bfloat16_rn(w);
            const __nv_bfloat16 l = __float2bfloat16_rn(w - __bfloat162float(h));
            const size_t o = (size_t)(n0 + n) * IND + k0 + tx;
            g_bhi[o] = h;
            g_blo[o] = l;
        }
    }
}

// ---------------------------------------------------------------------------
// K_convX: split x into hi/lo bf16; also zero g_dot/g_zn2 + init accumulators
// ---------------------------------------------------------------------------
__global__ __launch_bounds__(256)
void k_convX(const float* __restrict__ X) {
    const int bid = blockIdx.x;
    const int t   = threadIdx.x;
    if (bid == 0) {
        if (t < PP) g_minBits[t] = 0x7f7fffffu;
        if (t == 0) { g_pz_sum = 0.f; g_cl_sum = 0.f; g_num_cnt = 0; }
    }
    if (bid < 1024)               g_dot[bid * 256 + t] = 0.f;
    else if (bid < 1040)          g_zn2[(bid - 1024) * 256 + t] = 0.f;

    const int i = bid * 256 + t;                        // float4 index
    const float4 v = ((const float4*)X)[i];
    const __nv_bfloat16 h0 = __float2bfloat16_rn(v.x);
    const __nv_bfloat16 h1 = __float2bfloat16_rn(v.y);
    const __nv_bfloat16 h2 = __float2bfloat16_rn(v.z);
    const __nv_bfloat16 h3 = __float2bfloat16_rn(v.w);
    const __nv_bfloat16 l0 = __float2bfloat16_rn(v.x - __bfloat162float(h0));
    const __nv_bfloat16 l1 = __float2bfloat16_rn(v.y - __bfloat162float(h1));
    const __nv_bfloat16 l2 = __float2bfloat16_rn(v.z - __bfloat162float(h2));
    const __nv_bfloat16 l3 = __float2bfloat16_rn(v.w - __bfloat162float(h3));
    const uint32_t hp0 = ((uint32_t)__bfloat16_as_ushort(h1) << 16) | __bfloat16_as_ushort(h0);
    const uint32_t hp1 = ((uint32_t)__bfloat16_as_ushort(h3) << 16) | __bfloat16_as_ushort(h2);
    const uint32_t lp0 = ((uint32_t)__bfloat16_as_ushort(l1) << 16) | __bfloat16_as_ushort(l0);
    const uint32_t lp1 = ((uint32_t)__bfloat16_as_ushort(l3) << 16) | __bfloat16_as_ushort(l2);
    ((uint2*)g_xhi)[i] = make_uint2(hp0, hp1);
    ((uint2*)g_xlo)[i] = make_uint2(lp0, lp1);
}

// ---------------------------------------------------------------------------
// K_gemm_hmma: z = x@W+b (bf16x3 HMMA) + fused dot GEMM + zn2.
// R12 config (best measured): CTA tile 128x64, 512 threads, 1 CTA/SM.
// ---------------------------------------------------------------------------
__global__ __launch_bounds__(512, 1)
void k_gemm_hmma(const float* __restrict__ bias) {
    extern __shared__ __align__(128) char sm[];
    const uint32_t smb = smem_u32(sm);
    float* zn2s = (float*)(sm + 2 * GBUF);

    const int tid  = threadIdx.x;
    const int wid  = tid >> 5;
    const int lane = tid & 31;
    const int gid  = lane >> 2;
    const int tig  = lane & 3;
    const int m0   = blockIdx.x * 128;
    const int n0   = blockIdx.y * 64;
    const int wm   = (wid & 3) * 32;
    const int wn   = (wid >> 2) * 16;

    const int arow = lane & 15;
    const int acol = (lane >> 4) << 3;
    const int brow = (lane & 7) + ((lane >> 4) << 3);
    const int bcol = ((lane >> 3) & 1) << 3;

    auto stage = [&](int buf, int c) {
        const uint32_t bb = smb + buf * GBUF;
        const int k0 = c * 64;
#pragma unroll
        for (int i = 0; i < 2; i++) {
            const int idx = i * 512 + tid;
            const int r = idx >> 3, c8 = idx & 7;
            const size_t g = (size_t)(m0 + r) * IND + k0 + c8 * 8;
            const uint32_t d = bb + OFF_AHI + (uint32_t)(r * ASTR + c8 * 8) * 2;
            cp16(d,                       g_xhi + g);
            cp16(d + (OFF_ALO - OFF_AHI), g_xlo + g);
        }
        {
            const int r = tid >> 3, c8 = tid & 7;
            const size_t g = (size_t)(n0 + r) * IND + k0 + c8 * 8;
            const uint32_t d = bb + OFF_BHI + (uint32_t)(r * ASTR + c8 * 8) * 2;
            cp16(d,                       g_bhi + g);
            cp16(d + (OFF_BLO - OFF_BHI), g_blo + g);
        }
        asm volatile("cp.async.commit_group;" ::: "memory");
    };

    float acc[2][2][4];
#pragma unroll
    for (int mt = 0; mt < 2; mt++)
#pragma unroll
        for (int nt = 0; nt < 2; nt++)
#pragma unroll
            for (int q = 0; q < 4; q++) acc[mt][nt][q] = 0.f;

    stage(0, 0);

#pragma unroll 1
    for (int c = 0; c < 12; c++) {
        const int buf = c & 1;
        if (c < 11) {
            stage(buf ^ 1, c + 1);
            asm volatile("cp.async.wait_group 1;" ::: "memory");
        } else {
            asm volatile("cp.async.wait_group 0;" ::: "memory");
        }
        __syncthreads();

        const uint32_t bb = smb + buf * GBUF;
#pragma unroll
        for (int ks = 0; ks < 4; ks++) {
            const int kk = ks * 16;
            uint32_t Ahif[2][4], Alof[2][4];
#pragma unroll
            for (int mt = 0; mt < 2; mt++) {
                const uint32_t a = bb + OFF_AHI
                    + (uint32_t)((wm + mt * 16 + arow) * ASTR + kk + acol) * 2;
                ldmx4(Ahif[mt], a);
                ldmx4(Alof[mt], a + (OFF_ALO - OFF_AHI));
            }
            uint32_t Bhif[2][2], Blof[2][2];
            {
                const uint32_t a = bb + OFF_BHI
                    + (uint32_t)((wn + brow) * ASTR + kk + bcol) * 2;
                uint32_t rh[4], rl[4];
                ldmx4(rh, a);
                ldmx4(rl, a + (OFF_BLO - OFF_BHI));
                Bhif[0][0] = rh[0]; Bhif[0][1] = rh[1];
                Bhif[1][0] = rh[2]; Bhif[1][1] = rh[3];
                Blof[0][0] = rl[0]; Blof[0][1] = rl[1];
                Blof[1][0] = rl[2]; Blof[1][1] = rl[3];
            }
#pragma unroll
            for (int mt = 0; mt < 2; mt++)
#pragma unroll
                for (int nt = 0; nt < 2; nt++)
                    mma16816(acc[mt][nt], Ahif[mt], Bhif[nt]);
#pragma unroll
            for (int mt = 0; mt < 2; mt++)
#pragma unroll
                for (int nt = 0; nt < 2; nt++)
                    mma16816(acc[mt][nt], Ahif[mt], Blof[nt]);
#pragma unroll
            for (int mt = 0; mt < 2; mt++)
#pragma unroll
                for (int nt = 0; nt < 2; nt++)
                    mma16816(acc[mt][nt], Alof[mt], Bhif[nt]);
        }
        __syncthreads();
    }

    // ===== fused epilogue: z -> bf16 smem tile, zn2, dot GEMM =====
    if (tid < 128) zn2s[tid] = 0.f;

    // prefetch proto slice [64 p][64 d @ n0] into buf0 B region
    {
        const int r = tid >> 3, c8 = tid & 7;
        const size_t g = (size_t)r * DD + n0 + c8 * 8;
        const uint32_t d = smb + OFF_BHI + (uint32_t)(r * ASTR + c8 * 8) * 2;
        cp16(d,                       g_phi + g);
        cp16(d + (OFF_BLO - OFF_BHI), g_plo + g);
        asm volatile("cp.async.commit_group;" ::: "memory");
    }
    __syncthreads();

    // bias add + zn2 partials + z bf16 hi/lo into buf0 A region
#pragma unroll
    for (int nt = 0; nt < 2; nt++) {
        const int colg = n0 + wn + nt * 8 + tig * 2;
        const int coll = wn + nt * 8 + tig * 2;
        const float2 bv = *(const float2*)&bias[colg];
#pragma unroll
        for (int mt = 0; mt < 2; mt++) {
            const int rowl = wm + mt * 16 + gid;
            const float z0 = acc[mt][nt][0] + bv.x;
            const float z1 = acc[mt][nt][1] + bv.y;
            const float z2 = acc[mt][nt][2] + bv.x;
            const float z3 = acc[mt][nt][3] + bv.y;
            atomicAdd(&zn2s[rowl],     z0 * z0 + z1 * z1);
            atomicAdd(&zn2s[rowl + 8], z2 * z2 + z3 * z3);
            const __nv_bfloat16 h0 = __float2bfloat16_rn(z0);
            const __nv_bfloat16 h1 = __float2bfloat16_rn(z1);
            const __nv_bfloat16 h2 = __float2bfloat16_rn(z2);
            const __nv_bfloat16 h3 = __float2bfloat16_rn(z3);
            const uint32_t hp0 = ((uint32_t)__bfloat16_as_ushort(h1) << 16) | __bfloat16_as_ushort(h0);
            const uint32_t hp1 = ((uint32_t)__bfloat16_as_ushort(h3) << 16) | __bfloat16_as_ushort(h2);
            const uint32_t lp0 = bfpack(z0 - __bfloat162float(h0), z1 - __bfloat162float(h1));
            const uint32_t lp1 = bfpack(z2 - __bfloat162float(h2), z3 - __bfloat162float(h3));
            char* pa = sm + OFF_AHI + (uint32_t)(rowl * ASTR + coll) * 2;
            *(uint32_t*)(pa)                = hp0;
            *(uint32_t*)(pa + 8 * ASTR * 2) = hp1;
            char* pl = sm + OFF_ALO + (uint32_t)(rowl * ASTR + coll) * 2;
            *(uint32_t*)(pl)                = lp0;
            *(uint32_t*)(pl + 8 * ASTR * 2) = lp1;
        }
    }
    asm volatile("cp.async.wait_group 0;" ::: "memory");
    __syncthreads();

    // dot GEMM: M128 x N64(protos) x K64, 3 passes
    float acc2[2][2][4];
#pragma unroll
    for (int mt = 0; mt < 2; mt++)
#pragma unroll
        for (int nt = 0; nt < 2; nt++)
#pragma unroll
            for (int q = 0; q < 4; q++) acc2[mt][nt][q] = 0.f;

#pragma unroll
    for (int ks = 0; ks < 4; ks++) {
        const int kk = ks * 16;
        uint32_t Ahif[2][4], Alof[2][4];
#pragma unroll
        for (int mt = 0; mt < 2; mt++) {
            const uint32_t a = smb + OFF_AHI
                + (uint32_t)((wm + mt * 16 + arow) * ASTR + kk + acol) * 2;
            ldmx4(Ahif[mt], a);
            ldmx4(Alof[mt], a + (OFF_ALO - OFF_AHI));
        }
        uint32_t Bhif[2][2], Blof[2][2];
        {
            const uint32_t a = smb + OFF_BHI
                + (uint32_t)((wn + brow) * ASTR + kk + bcol) * 2;
            uint32_t rh[4], rl[4];
            ldmx4(rh, a);
            ldmx4(rl, a + (OFF_BLO - OFF_BHI));
            Bhif[0][0] = rh[0]; Bhif[0][1] = rh[1];
            Bhif[1][0] = rh[2]; Bhif[1][1] = rh[3];
            Blof[0][0] = rl[0]; Blof[0][1] = rl[1];
            Blof[1][0] = rl[2]; Blof[1][1] = rl[3];
        }
#pragma unroll
        for (int mt = 0; mt < 2; mt++)
#pragma unroll
            for (int nt = 0; nt < 2; nt++)
                mma16816(acc2[mt][nt], Ahif[mt], Bhif[nt]);
#pragma unroll
        for (int mt = 0; mt < 2; mt++)
#pragma unroll
            for (int nt = 0; nt < 2; nt++)
                mma16816(acc2[mt][nt], Ahif[mt], Blof[nt]);
#pragma unroll
        for (int mt = 0; mt < 2; mt++)
#pragma unroll
            for (int nt = 0; nt < 2; nt++)
                mma16816(acc2[mt][nt], Alof[mt], Bhif[nt]);
    }

    // accumulate dot partials (4 d-slice blocks per sample row)
#pragma unroll
    for (int nt = 0; nt < 2; nt++) {
        const int p = wn + nt * 8 + tig * 2;
#pragma unroll
        for (int mt = 0; mt < 2; mt++) {
            const int row = m0 + wm + mt * 16 + gid;
            atomicAdd(&g_dot[(size_t)row * PP + p],           acc2[mt][nt][0]);
            atomicAdd(&g_dot[(size_t)row * PP + p + 1],       acc2[mt][nt][1]);
            atomicAdd(&g_dot[(size_t)(row + 8) * PP + p],     acc2[mt][nt][2]);
            atomicAdd(&g_dot[(size_t)(row + 8) * PP + p + 1], acc2[mt][nt][3]);
        }
    }
    __syncthreads();
    if (tid < 128) atomicAdd(&g_zn2[m0 + tid], zn2s[tid]);
}

// ---------------------------------------------------------------------------
// K_post_tokens (fused): block = 4 samples. Phase 1: cos/dist + all loss
// reductions from g_dot/g_zn2, cos kept in smem (no g_cos round-trip).
// Phase 2: stream 256 KB of token writes per block. grid = 1024 x 256.
// ---------------------------------------------------------------------------
__global__ __launch_bounds__(256)
void k_post_tokens(const long long* __restrict__ labels,
                   const float* __restrict__ proto,
                   float* __restrict__ out) {
    __shared__ float s_cos[4][PP];
    __shared__ unsigned int bmin[PP];
    __shared__ float wmin[8], wmax[8];
    __shared__ int   wcnt[8];
    __shared__ float s_pz, s_cl;
    __shared__ int   s_cnt;

    const int tid = threadIdx.x;
    const int nb  = blockIdx.x * 4;      // first sample of this block
    const int s   = tid >> 6;            // 0..3 sample
    const int p   = tid & 63;            // 0..63 prototype
    const int wid = tid >> 5;            // warp 2s covers p<32 (pos half)
    const int lane = tid & 31;

    if (tid < PP) bmin[tid] = 0x7f7fffffu;
    if (tid == 0) { s_pz = 0.f; s_cl = 0.f; s_cnt = 0; }
    __syncthreads();

    // ---- phase 1: per-(sample, proto) cos/dist ----
    const float zn2 = g_zn2[nb + s];
    const float rz  = 1.0f / fmaxf(sqrtf(zn2), 1e-8f);
    const float dt  = g_dot[(size_t)(nb + s) * PP + p];
    const float cosv = dt * rz * __ldg(&g_pnorm_inv[p]);
    const float dstv = sqrtf(fmaxf(zn2 + __ldg(&g_pnorm2[p]) - 2.0f * dt, 0.f));
    s_cos[s][p] = cosv;
    atomicMin(&bmin[p], __float_as_uint(dstv));

    // warp reductions (warp = one pos/neg half of one sample)
    float mnD = dstv;
    float mx  = cosv;
    int   c   = (cosv > 0.5f);
#pragma unroll
    for (int o = 16; o; o >>= 1) {
        mnD = fminf(mnD, __shfl_xor_sync(0xffffffffu, mnD, o));
        mx  = fmaxf(mx,  __shfl_xor_sync(0xffffffffu, mx,  o));
        c  += __shfl_xor_sync(0xffffffffu, c, o);
    }
    if (lane == 0) { wmin[wid] = mnD; wmax[wid] = mx; wcnt[wid] = c; }
    __syncthreads();

    if (tid < 4) {
        const float minD = fminf(wmin[2 * tid], wmin[2 * tid + 1]);
        const float mp   = wmax[2 * tid];        // pos half (p < 32)
        const float mn   = wmax[2 * tid + 1];    // neg half
        const int   cnt  = wcnt[2 * tid] + wcnt[2 * tid + 1];
        const long long lb = labels[nb + tid];
        atomicAdd(&s_pz, minD);
        atomicAdd(&s_cl, (lb == 1) ? (1.0f - mp) : (1.0f - mn));
        if (cnt > PP / 4) atomicAdd(&s_cnt, 1);
    }
    __syncthreads();

    if (tid == 0) {
        atomicAdd(&g_pz_sum, s_pz);
        atomicAdd(&g_cl_sum, s_cl);
        if (s_cnt) atomicAdd(&g_num_cnt, s_cnt);
    }
    if (tid < PP) atomicMin(&g_minBits[tid], bmin[tid]);

    // ---- phase 2: token writes, 4 samples x 4096 float4 = 16384 float4 ----
    const float4* proto4 = (const float4*)proto;
    float4* out4 = (float4*)out + (size_t)nb * (PP * DD / 4);
#pragma unroll 8
    for (int it = 0; it < 64; it++) {
        const int idx = it * 256 + tid;
        const int sl  = idx >> 12;
        const int pl  = (idx >> 6) & 63;
        const int d4  = idx & 63;
        const float cv = s_cos[sl][pl];
        const float4 pr = __ldg(proto4 + pl * 64 + d4);
        out4[idx] = make_float4(cv * pr.x, cv * pr.y, cv * pr.z, cv * pr.w);
    }
}

// ---------------------------------------------------------------------------
// K_final: combine scalar loss terms
// ---------------------------------------------------------------------------
__global__ void k_final(float* __restrict__ out, int loss_idx) {
    __shared__ float s[PP];
    __shared__ float pp[PP];
    const int t = threadIdx.x;
    if (t < PP) {
        s[t]  = __uint_as_float(g_minBits[t]);
        pp[t] = g_pp_part[t];
    }
    __syncthreads();
    if (t == 0) {
        float zp = 0.f, pps = 0.f;
#pragma unroll
        for (int k = 0; k < PP; k++) { zp += s[k]; pps += pp[k]; }
        const float l_zp  = zp / (float)PP;
        const float l_pz  = g_pz_sum / (float)NS;
        const float l_pp  = pps / (float)(PP * (PP - 1));
        const float l_num = (float)g_num_cnt;
        const float l_cl  = g_cl_sum / (float)NS;
        out[loss_idx] = l_zp + l_pz + l_pp + l_num + l_cl + l_cl;
    }
}

// ---------------------------------------------------------------------------
// kernel_launch
// ---------------------------------------------------------------------------
extern "C" void kernel_launch(void* const* d_in, const int* in_sizes, int n_in,
                              void* d_out, int out_size) {
    const float*     x      = nullptr;
    const long long* labels = nullptr;
    const float*     W      = nullptr;
    const float*     b      = nullptr;
    const float*     proto  = nullptr;
    for (int i = 0; i < n_in; i++) {
        switch (in_sizes[i]) {
            case NS * IND: x      = (const float*)d_in[i];     break;
            case NS:       labels = (const long long*)d_in[i]; break;
            case IND * DD: W      = (const float*)d_in[i];     break;
            case DD:       b      = (const float*)d_in[i];     break;
            case PP * DD:  proto  = (const float*)d_in[i];     break;
        }
    }
    if (!x || !labels || !W || !b || !proto) {
        x      = (const float*)d_in[0];
        labels = (const long long*)d_in[1];
        W      = (const float*)d_in[2];
        b      = (const float*)d_in[3];
        proto  = (const float*)d_in[4];
    }
    float* out = (float*)d_out;

    cudaFuncSetAttribute(k_gemm_hmma, cudaFuncAttributeMaxDynamicSharedMemorySize,
                         SMEM_GEMM);

    k_prep       <<<NPROTO + NCONVW, 256>>>(proto, W);               // 1
    k_convX      <<<NS * IND / 4 / 256, 256>>>(x);                   // 2 (+init/zero)
    k_gemm_hmma  <<<dim3(NS / 128, DD / 64), 512, SMEM_GEMM>>>(b);   // 3
    k_post_tokens<<<NS / 4, 256>>>(labels, proto, out);              // 4 <- profiled
    k_final      <<<1, 64>>>(out, out_size - 1);                     // 5
}

// round 15
// speedup vs baseline: 1.1455x; 1.1455x over previous
#include <cuda_runtime.h>
#include <cuda_bf16.h>
#include <math.h>
#include <float.h>
#include <stdint.h>

// ---------------------------------------------------------------------------
// Problem constants
// ---------------------------------------------------------------------------
#define NS   4096        // samples
#define IND  768         // input dim
#define DD   256         // prototype dim
#define PP   64          // prototypes
#define PPOS 32          // P/2

// ---------------------------------------------------------------------------
// Device scratch (static — no runtime allocation allowed)
// ---------------------------------------------------------------------------
__device__ float          g_dot[NS * PP];        // z·proto dots (1 MB, atomic acc)
__device__ float          g_zn2[NS];             // per-sample ||z||^2
__device__ float          g_cos[NS * PP];        // cosine sims (1 MB)
__device__ __nv_bfloat16  g_xhi[NS * IND];       // x hi bf16, [M][K]
__device__ __nv_bfloat16  g_xlo[NS * IND];       // x lo bf16
__device__ __nv_bfloat16  g_bhi[DD * IND];       // W^T hi, [N][K]
__device__ __nv_bfloat16  g_blo[DD * IND];       // W^T lo
__device__ __nv_bfloat16  g_phi[PP * DD];        // proto hi bf16, [P][D]
__device__ __nv_bfloat16  g_plo[PP * DD];        // proto lo bf16
__device__ float          g_pnorm2[PP];
__device__ float          g_pnorm_inv[PP];
__device__ float          g_pp_part[PP];
__device__ unsigned int   g_minBits[PP];
__device__ float          g_pz_sum;
__device__ float          g_cl_sum;
__device__ int            g_num_cnt;

__device__ __forceinline__ float warpSum(float v) {
#pragma unroll
    for (int o = 16; o; o >>= 1) v += __shfl_xor_sync(0xffffffffu, v, o);
    return v;
}

__device__ __forceinline__ uint32_t smem_u32(const void* p) {
    uint32_t a;
    asm("{ .reg .u64 t; cvta.to.shared.u64 t, %1; cvt.u32.u64 %0, t; }"
        : "=r"(a) : "l"(p));
    return a;
}

__device__ __forceinline__ void cp16(uint32_t sdst, const void* gsrc) {
    asm volatile("cp.async.cg.shared.global [%0], [%1], 16;"
                 :: "r"(sdst), "l"(gsrc) : "memory");
}

// m16n8k16 row.col f32.bf16.bf16.f32
__device__ __forceinline__ void mma16816(float (&d)[4], const uint32_t (&a)[4],
                                         const uint32_t (&b)[2]) {
    asm volatile(
        "mma.sync.aligned.m16n8k16.row.col.f32.bf16.bf16.f32 "
        "{%0,%1,%2,%3}, {%4,%5,%6,%7}, {%8,%9}, {%0,%1,%2,%3};"
        : "+f"(d[0]), "+f"(d[1]), "+f"(d[2]), "+f"(d[3])
        : "r"(a[0]), "r"(a[1]), "r"(a[2]), "r"(a[3]),
          "r"(b[0]), "r"(b[1]));
}

__device__ __forceinline__ void ldmx4(uint32_t (&r)[4], uint32_t addr) {
    asm volatile("ldmatrix.sync.aligned.m8n8.x4.shared.b16 {%0,%1,%2,%3}, [%4];"
                 : "=r"(r[0]), "=r"(r[1]), "=r"(r[2]), "=r"(r[3]) : "r"(addr));
}

__device__ __forceinline__ uint32_t bfpack(float a, float b) {
    const __nv_bfloat16 ha = __float2bfloat16_rn(a);
    const __nv_bfloat16 hb = __float2bfloat16_rn(b);
    return ((uint32_t)__bfloat16_as_ushort(hb) << 16) | __bfloat16_as_ushort(ha);
}

// GEMM smem layout (bf16, padded stride 72 bf16 = 144 B), CTA tile 128x64
#define ASTR     72
#define OFF_AHI  0
#define OFF_ALO  18432            // 128*72*2
#define OFF_BHI  36864
#define OFF_BLO  46080            // +64*72*2
#define GBUF     55296
#define SMEM_GEMM (2 * GBUF + 512)   // + zn2s[128]

#define NPROTO   PP                       // 64 proto blocks
#define NCONVW   ((IND / 32) * (DD / 32)) // 192 convW blocks
#define NCONVX   (NS * IND / 4 / 256)     // 3072 convX blocks
#define NPREP    (NPROTO + NCONVW + NCONVX)

// ---------------------------------------------------------------------------
// K_prep (mega): [0,64) proto norms + pp partials + proto hi/lo (slow, FIRST);
//                [64,256) W hi/lo split + transpose;
//                [256,3328) x hi/lo split + init/zero of accumulators.
// ---------------------------------------------------------------------------
__global__ __launch_bounds__(256)
void k_prep(const float* __restrict__ proto, const float* __restrict__ W,
            const float* __restrict__ X) {
    const int bid = blockIdx.x;
    const int t   = threadIdx.x;

    if (bid < NPROTO) {
        const int i = bid;
        __shared__ float pi[DD];
        __shared__ float red[8];
        __shared__ float ddist[PP];

        float v = proto[i * DD + t];
        pi[t] = v;
        const __nv_bfloat16 h = __float2bfloat16_rn(v);
        g_phi[i * DD + t] = h;
        g_plo[i * DD + t] = __float2bfloat16_rn(v - __bfloat162float(h));

        float nrm = warpSum(v * v);
        if ((t & 31) == 0) red[t >> 5] = nrm;
        __syncthreads();
        if (t == 0) {
            float s = 0.f;
#pragma unroll
            for (int w = 0; w < 8; w++) s += red[w];
            g_pnorm2[i]    = s;
            g_pnorm_inv[i] = 1.0f / fmaxf(sqrtf(s), 1e-8f);
        }
        __syncthreads();

        const int j = t >> 2;
        const int q = t & 3;
        const float* pj = proto + j * DD + q * 64;
        float s = 0.f;
#pragma unroll 8
        for (int d = 0; d < 64; d++) {
            float df = pi[q * 64 + d] - pj[d];
            s += df * df;
        }
        s += __shfl_down_sync(0xffffffffu, s, 1);
        s += __shfl_down_sync(0xffffffffu, s, 2);
        if (q == 0) ddist[j] = (j == i) ? 0.f : sqrtf(fmaxf(s, 0.f));
        __syncthreads();
        if (t == 0) {
            float acc = 0.f;
#pragma unroll
            for (int k = 0; k < PP; k++) acc += ddist[k];
            g_pp_part[i] = acc;
        }
        return;
    }

    if (bid < NPROTO + NCONVW) {
        // ---- convW: smem-tiled transpose + hi/lo split ----
        __shared__ float tile[32][33];
        const int bid2 = bid - NPROTO;
        const int k0 = (bid2 % (IND / 32)) * 32;
        const int n0 = (bid2 / (IND / 32)) * 32;
        const int tx = t & 31;
        const int ty = t >> 5;

#pragma unroll
        for (int r = 0; r < 4; r++) {
            const int k = ty + r * 8;
            tile[k][tx] = W[(size_t)(k0 + k) * DD + n0 + tx];
        }
        __syncthreads();

#pragma unroll
        for (int r = 0; r < 4; r++) {
            const int n = ty + r * 8;
            const float w = tile[tx][n];
            const __nv_bfloat16 h = __float2bfloat16_rn(w);
            const __nv_bfloat16 l = __float2bfloat16_rn(w - __bfloat162float(h));
            const size_t o = (size_t)(n0 + n) * IND + k0 + tx;
            g_bhi[o] = h;
            g_blo[o] = l;
        }
        return;
    }

    // ---- convX: x hi/lo split + init/zero ----
    {
        const int bid3 = bid - NPROTO - NCONVW;   // 0..3071
        if (bid3 == 0) {
            if (t < PP) g_minBits[t] = 0x7f7fffffu;
            if (t == 0) { g_pz_sum = 0.f; g_cl_sum = 0.f; g_num_cnt = 0; }
        }
        if (bid3 < 1024)      g_dot[bid3 * 256 + t] = 0.f;
        else if (bid3 < 1040) g_zn2[(bid3 - 1024) * 256 + t] = 0.f;

        const int i = bid3 * 256 + t;             // float4 index
        const float4 v = ((const float4*)X)[i];
        const __nv_bfloat16 h0 = __float2bfloat16_rn(v.x);
        const __nv_bfloat16 h1 = __float2bfloat16_rn(v.y);
        const __nv_bfloat16 h2 = __float2bfloat16_rn(v.z);
        const __nv_bfloat16 h3 = __float2bfloat16_rn(v.w);
        const __nv_bfloat16 l0 = __float2bfloat16_rn(v.x - __bfloat162float(h0));
        const __nv_bfloat16 l1 = __float2bfloat16_rn(v.y - __bfloat162float(h1));
        const __nv_bfloat16 l2 = __float2bfloat16_rn(v.z - __bfloat162float(h2));
        const __nv_bfloat16 l3 = __float2bfloat16_rn(v.w - __bfloat162float(h3));
        const uint32_t hp0 = ((uint32_t)__bfloat16_as_ushort(h1) << 16) | __bfloat16_as_ushort(h0);
        const uint32_t hp1 = ((uint32_t)__bfloat16_as_ushort(h3) << 16) | __bfloat16_as_ushort(h2);
        const uint32_t lp0 = ((uint32_t)__bfloat16_as_ushort(l1) << 16) | __bfloat16_as_ushort(l0);
        const uint32_t lp1 = ((uint32_t)__bfloat16_as_ushort(l3) << 16) | __bfloat16_as_ushort(l2);
        ((uint2*)g_xhi)[i] = make_uint2(hp0, hp1);
        ((uint2*)g_xlo)[i] = make_uint2(lp0, lp1);
    }
}

// ---------------------------------------------------------------------------
// K_gemm_hmma: z = x@W+b (bf16x3 HMMA) + fused dot GEMM + zn2.
// R12 config (measured best): CTA tile 128x64, 512 threads, 1 CTA/SM.
// ---------------------------------------------------------------------------
__global__ __launch_bounds__(512, 1)
void k_gemm_hmma(const float* __restrict__ bias) {
    extern __shared__ __align__(128) char sm[];
    const uint32_t smb = smem_u32(sm);
    float* zn2s = (float*)(sm + 2 * GBUF);

    const int tid  = threadIdx.x;
    const int wid  = tid >> 5;
    const int lane = tid & 31;
    const int gid  = lane >> 2;
    const int tig  = lane & 3;
    const int m0   = blockIdx.x * 128;
    const int n0   = blockIdx.y * 64;
    const int wm   = (wid & 3) * 32;
    const int wn   = (wid >> 2) * 16;

    const int arow = lane & 15;
    const int acol = (lane >> 4) << 3;
    const int brow = (lane & 7) + ((lane >> 4) << 3);
    const int bcol = ((lane >> 3) & 1) << 3;

    auto stage = [&](int buf, int c) {
        const uint32_t bb = smb + buf * GBUF;
        const int k0 = c * 64;
#pragma unroll
        for (int i = 0; i < 2; i++) {
            const int idx = i * 512 + tid;
            const int r = idx >> 3, c8 = idx & 7;
            const size_t g = (size_t)(m0 + r) * IND + k0 + c8 * 8;
            const uint32_t d = bb + OFF_AHI + (uint32_t)(r * ASTR + c8 * 8) * 2;
            cp16(d,                       g_xhi + g);
            cp16(d + (OFF_ALO - OFF_AHI), g_xlo + g);
        }
        {
            const int r = tid >> 3, c8 = tid & 7;
            const size_t g = (size_t)(n0 + r) * IND + k0 + c8 * 8;
            const uint32_t d = bb + OFF_BHI + (uint32_t)(r * ASTR + c8 * 8) * 2;
            cp16(d,                       g_bhi + g);
            cp16(d + (OFF_BLO - OFF_BHI), g_blo + g);
        }
        asm volatile("cp.async.commit_group;" ::: "memory");
    };

    float acc[2][2][4];
#pragma unroll
    for (int mt = 0; mt < 2; mt++)
#pragma unroll
        for (int nt = 0; nt < 2; nt++)
#pragma unroll
            for (int q = 0; q < 4; q++) acc[mt][nt][q] = 0.f;

    stage(0, 0);

#pragma unroll 1
    for (int c = 0; c < 12; c++) {
        const int buf = c & 1;
        if (c < 11) {
            stage(buf ^ 1, c + 1);
            asm volatile("cp.async.wait_group 1;" ::: "memory");
        } else {
            asm volatile("cp.async.wait_group 0;" ::: "memory");
        }
        __syncthreads();

        const uint32_t bb = smb + buf * GBUF;
#pragma unroll
        for (int ks = 0; ks < 4; ks++) {
            const int kk = ks * 16;
            uint32_t Ahif[2][4], Alof[2][4];
#pragma unroll
            for (int mt = 0; mt < 2; mt++) {
                const uint32_t a = bb + OFF_AHI
                    + (uint32_t)((wm + mt * 16 + arow) * ASTR + kk + acol) * 2;
                ldmx4(Ahif[mt], a);
                ldmx4(Alof[mt], a + (OFF_ALO - OFF_AHI));
            }
            uint32_t Bhif[2][2], Blof[2][2];
            {
                const uint32_t a = bb + OFF_BHI
                    + (uint32_t)((wn + brow) * ASTR + kk + bcol) * 2;
                uint32_t rh[4], rl[4];
                ldmx4(rh, a);
                ldmx4(rl, a + (OFF_BLO - OFF_BHI));
                Bhif[0][0] = rh[0]; Bhif[0][1] = rh[1];
                Bhif[1][0] = rh[2]; Bhif[1][1] = rh[3];
                Blof[0][0] = rl[0]; Blof[0][1] = rl[1];
                Blof[1][0] = rl[2]; Blof[1][1] = rl[3];
            }
#pragma unroll
            for (int mt = 0; mt < 2; mt++)
#pragma unroll
                for (int nt = 0; nt < 2; nt++)
                    mma16816(acc[mt][nt], Ahif[mt], Bhif[nt]);
#pragma unroll
            for (int mt = 0; mt < 2; mt++)
#pragma unroll
                for (int nt = 0; nt < 2; nt++)
                    mma16816(acc[mt][nt], Ahif[mt], Blof[nt]);
#pragma unroll
            for (int mt = 0; mt < 2; mt++)
#pragma unroll
                for (int nt = 0; nt < 2; nt++)
                    mma16816(acc[mt][nt], Alof[mt], Bhif[nt]);
        }
        __syncthreads();
    }

    // ===== fused epilogue: z -> bf16 smem tile, zn2, dot GEMM =====
    if (tid < 128) zn2s[tid] = 0.f;

    // prefetch proto slice [64 p][64 d @ n0] into buf0 B region
    {
        const int r = tid >> 3, c8 = tid & 7;
        const size_t g = (size_t)r * DD + n0 + c8 * 8;
        const uint32_t d = smb + OFF_BHI + (uint32_t)(r * ASTR + c8 * 8) * 2;
        cp16(d,                       g_phi + g);
        cp16(d + (OFF_BLO - OFF_BHI), g_plo + g);
        asm volatile("cp.async.commit_group;" ::: "memory");
    }
    __syncthreads();

    // bias add + zn2 partials + z bf16 hi/lo into buf0 A region
#pragma unroll
    for (int nt = 0; nt < 2; nt++) {
        const int colg = n0 + wn + nt * 8 + tig * 2;
        const int coll = wn + nt * 8 + tig * 2;
        const float2 bv = *(const float2*)&bias[colg];
#pragma unroll
        for (int mt = 0; mt < 2; mt++) {
            const int rowl = wm + mt * 16 + gid;
            const float z0 = acc[mt][nt][0] + bv.x;
            const float z1 = acc[mt][nt][1] + bv.y;
            const float z2 = acc[mt][nt][2] + bv.x;
            const float z3 = acc[mt][nt][3] + bv.y;
            atomicAdd(&zn2s[rowl],     z0 * z0 + z1 * z1);
            atomicAdd(&zn2s[rowl + 8], z2 * z2 + z3 * z3);
            const __nv_bfloat16 h0 = __float2bfloat16_rn(z0);
            const __nv_bfloat16 h1 = __float2bfloat16_rn(z1);
            const __nv_bfloat16 h2 = __float2bfloat16_rn(z2);
            const __nv_bfloat16 h3 = __float2bfloat16_rn(z3);
            const uint32_t hp0 = ((uint32_t)__bfloat16_as_ushort(h1) << 16) | __bfloat16_as_ushort(h0);
            const uint32_t hp1 = ((uint32_t)__bfloat16_as_ushort(h3) << 16) | __bfloat16_as_ushort(h2);
            const uint32_t lp0 = bfpack(z0 - __bfloat162float(h0), z1 - __bfloat162float(h1));
            const uint32_t lp1 = bfpack(z2 - __bfloat162float(h2), z3 - __bfloat162float(h3));
            char* pa = sm + OFF_AHI + (uint32_t)(rowl * ASTR + coll) * 2;
            *(uint32_t*)(pa)                = hp0;
            *(uint32_t*)(pa + 8 * ASTR * 2) = hp1;
            char* pl = sm + OFF_ALO + (uint32_t)(rowl * ASTR + coll) * 2;
            *(uint32_t*)(pl)                = lp0;
            *(uint32_t*)(pl + 8 * ASTR * 2) = lp1;
        }
    }
    asm volatile("cp.async.wait_group 0;" ::: "memory");
    __syncthreads();

    // dot GEMM: M128 x N64(protos) x K64, 3 passes
    float acc2[2][2][4];
#pragma unroll
    for (int mt = 0; mt < 2; mt++)
#pragma unroll
        for (int nt = 0; nt < 2; nt++)
#pragma unroll
            for (int q = 0; q < 4; q++) acc2[mt][nt][q] = 0.f;

#pragma unroll
    for (int ks = 0; ks < 4; ks++) {
        const int kk = ks * 16;
        uint32_t Ahif[2][4], Alof[2][4];
#pragma unroll
        for (int mt = 0; mt < 2; mt++) {
            const uint32_t a = smb + OFF_AHI
                + (uint32_t)((wm + mt * 16 + arow) * ASTR + kk + acol) * 2;
            ldmx4(Ahif[mt], a);
            ldmx4(Alof[mt], a + (OFF_ALO - OFF_AHI));
        }
        uint32_t Bhif[2][2], Blof[2][2];
        {
            const uint32_t a = smb + OFF_BHI
                + (uint32_t)((wn + brow) * ASTR + kk + bcol) * 2;
            uint32_t rh[4], rl[4];
            ldmx4(rh, a);
            ldmx4(rl, a + (OFF_BLO - OFF_BHI));
            Bhif[0][0] = rh[0]; Bhif[0][1] = rh[1];
            Bhif[1][0] = rh[2]; Bhif[1][1] = rh[3];
            Blof[0][0] = rl[0]; Blof[0][1] = rl[1];
            Blof[1][0] = rl[2]; Blof[1][1] = rl[3];
        }
#pragma unroll
        for (int mt = 0; mt < 2; mt++)
#pragma unroll
            for (int nt = 0; nt < 2; nt++)
                mma16816(acc2[mt][nt], Ahif[mt], Bhif[nt]);
#pragma unroll
        for (int mt = 0; mt < 2; mt++)
#pragma unroll
            for (int nt = 0; nt < 2; nt++)
                mma16816(acc2[mt][nt], Ahif[mt], Blof[nt]);
#pragma unroll
        for (int mt = 0; mt < 2; mt++)
#pragma unroll
            for (int nt = 0; nt < 2; nt++)
                mma16816(acc2[mt][nt], Alof[mt], Bhif[nt]);
    }

    // accumulate dot partials (4 d-slice blocks per sample row)
#pragma unroll
    for (int nt = 0; nt < 2; nt++) {
        const int p = wn + nt * 8 + tig * 2;
#pragma unroll
        for (int mt = 0; mt < 2; mt++) {
            const int row = m0 + wm + mt * 16 + gid;
            atomicAdd(&g_dot[(size_t)row * PP + p],           acc2[mt][nt][0]);
            atomicAdd(&g_dot[(size_t)row * PP + p + 1],       acc2[mt][nt][1]);
            atomicAdd(&g_dot[(size_t)(row + 8) * PP + p],     acc2[mt][nt][2]);
            atomicAdd(&g_dot[(size_t)(row + 8) * PP + p + 1], acc2[mt][nt][3]);
        }
    }
    __syncthreads();
    if (tid < 128) atomicAdd(&g_zn2[m0 + tid], zn2s[tid]);
}

// ---------------------------------------------------------------------------
// K_post: per-sample cos/dist + loss reductions from g_dot/g_zn2. grid = 512.
// (R12 verbatim — 7.5 us measured)
// ---------------------------------------------------------------------------
__global__ __launch_bounds__(256)
void k_post(const long long* __restrict__ labels) {
    __shared__ unsigned int bmin[PP];
    __shared__ float s_pz, s_cl;
    __shared__ int   s_cnt;

    const int tid = threadIdx.x;
    const int s   = tid >> 5;
    const int pg  = tid & 31;
    const int p0  = pg * 2;
    const int n   = blockIdx.x * 8 + s;

    if (tid < PP) bmin[tid] = 0x7f7fffffu;
    if (tid == 0) { s_pz = 0.f; s_cl = 0.f; s_cnt = 0; }
    __syncthreads();

    const float zn2 = g_zn2[n];
    const float rz  = 1.0f / fmaxf(sqrtf(zn2), 1e-8f);
    const float2 dt = *(const float2*)&g_dot[(size_t)n * PP + p0];
    const float2 pinv = __ldg((const float2*)&g_pnorm_inv[p0]);
    const float2 pn2  = __ldg((const float2*)&g_pnorm2[p0]);

    const float cos0 = dt.x * rz * pinv.x;
    const float cos1 = dt.y * rz * pinv.y;
    const float dst0 = sqrtf(fmaxf(zn2 + pn2.x - 2.0f * dt.x, 0.f));
    const float dst1 = sqrtf(fmaxf(zn2 + pn2.y - 2.0f * dt.y, 0.f));

    *(float2*)&g_cos[(size_t)n * PP + p0] = make_float2(cos0, cos1);

    atomicMin(&bmin[p0],     __float_as_uint(dst0));
    atomicMin(&bmin[p0 + 1], __float_as_uint(dst1));

    float minD = fminf(dst0, dst1);
    const float mx = fmaxf(cos0, cos1);
    const bool pos = (pg < 16);
    float mp = pos ? mx : -FLT_MAX;
    float mn = pos ? -FLT_MAX : mx;
    int cnt = (cos0 > 0.5f) + (cos1 > 0.5f);
#pragma unroll
    for (int o = 16; o; o >>= 1) {
        minD = fminf(minD, __shfl_xor_sync(0xffffffffu, minD, o));
        mp   = fmaxf(mp,   __shfl_xor_sync(0xffffffffu, mp,   o));
        mn   = fmaxf(mn,   __shfl_xor_sync(0xffffffffu, mn,   o));
        cnt += __shfl_xor_sync(0xffffffffu, cnt, o);
    }
    if (pg == 0) {
        const long long lb = labels[n];
        atomicAdd(&s_pz, minD);
        atomicAdd(&s_cl, (lb == 1) ? (1.0f - mp) : (1.0f - mn));
        if (cnt > PP / 4) atomicAdd(&s_cnt, 1);
    }
    __syncthreads();

    if (tid == 0) {
        atomicAdd(&g_pz_sum, s_pz);
        atomicAdd(&g_cl_sum, s_cl);
        if (s_cnt) atomicAdd(&g_num_cnt, s_cnt);
    }
    if (tid < PP) atomicMin(&g_minBits[tid], bmin[tid]);
}

// ---------------------------------------------------------------------------
// K_tokens: out[n,p,d] = cos[n,p] * proto[p,d], 268 MB write stream.
// grid = 16384 x 256 (R12 verbatim, 39.3 us @ 67% DRAM). Block 0 thread 0
// additionally combines the scalar loss (k_post completed before launch).
// ---------------------------------------------------------------------------
__global__ __launch_bounds__(256)
void k_tokens(const float* __restrict__ proto, float* __restrict__ out,
              int loss_idx) {
    if (blockIdx.x == 0 && threadIdx.x == 0) {
        float zp = 0.f, pps = 0.f;
#pragma unroll
        for (int k = 0; k < PP; k++) {
            zp  += __uint_as_float(g_minBits[k]);
            pps += g_pp_part[k];
        }
        const float l_zp  = zp / (float)PP;
        const float l_pz  = g_pz_sum / (float)NS;
        const float l_pp  = pps / (float)(PP * (PP - 1));
        const float l_num = (float)g_num_cnt;
        const float l_cl  = g_cl_sum / (float)NS;
        out[loss_idx] = l_zp + l_pz + l_pp + l_num + l_cl + l_cl;
    }

    const int base = blockIdx.x * 1024;
    const float4* proto4 = (const float4*)proto;
    float4* out4 = (float4*)out;
#pragma unroll
    for (int j = 0; j < 4; j++) {
        const int idx = base + j * 256 + threadIdx.x;
        const int d4  = idx & 63;
        const int p   = (idx >> 6) & 63;
        const float c = __ldg(&g_cos[idx >> 6]);
        const float4 pr = __ldg(proto4 + p * 64 + d4);
        out4[idx] = make_float4(c * pr.x, c * pr.y, c * pr.z, c * pr.w);
    }
}

// ---------------------------------------------------------------------------
// kernel_launch — 4 launches total
// ---------------------------------------------------------------------------
extern "C" void kernel_launch(void* const* d_in, const int* in_sizes, int n_in,
                              void* d_out, int out_size) {
    const float*     x      = nullptr;
    const long long* labels = nullptr;
    const float*     W      = nullptr;
    const float*     b      = nullptr;
    const float*     proto  = nullptr;
    for (int i = 0; i < n_in; i++) {
        switch (in_sizes[i]) {
            case NS * IND: x      = (const float*)d_in[i];     break;
            case NS:       labels = (const long long*)d_in[i]; break;
            case IND * DD: W      = (const float*)d_in[i];     break;
            case DD:       b      = (const float*)d_in[i];     break;
            case PP * DD:  proto  = (const float*)d_in[i];     break;
        }
    }
    if (!x || !labels || !W || !b || !proto) {
        x      = (const float*)d_in[0];
        labels = (const long long*)d_in[1];
        W      = (const float*)d_in[2];
        b      = (const float*)d_in[3];
        proto  = (const float*)d_in[4];
    }
    float* out = (float*)d_out;

    cudaFuncSetAttribute(k_gemm_hmma, cudaFuncAttributeMaxDynamicSharedMemorySize,
                         SMEM_GEMM);

    k_prep     <<<NPREP, 256>>>(proto, W, x);                        // 1
    k_gemm_hmma<<<dim3(NS / 128, DD / 64), 512, SMEM_GEMM>>>(b);     // 2
    k_post     <<<NS / 8, 256>>>(labels);                            // 3
    k_tokens   <<<NS * PP * DD / 4 / 1024, 256>>>(proto, out,        // 4 <- profiled
                                                  out_size - 1);
}

// round 16
// speedup vs baseline: 1.1749x; 1.0257x over previous
#include <cuda_runtime.h>
#include <cuda_bf16.h>
#include <math.h>
#include <float.h>
#include <stdint.h>

// ---------------------------------------------------------------------------
// Problem constants
// ---------------------------------------------------------------------------
#define NS   4096        // samples
#define IND  768         // input dim
#define DD   256         // prototype dim
#define PP   64          // prototypes
#define PPOS 32          // P/2

// ---------------------------------------------------------------------------
// Device scratch (static — no runtime allocation allowed)
// ---------------------------------------------------------------------------
__device__ float          g_dot[NS * PP];        // z·proto dots (1 MB, atomic acc)
__device__ float          g_zn2[NS];             // per-sample ||z||^2
__device__ __nv_bfloat16  g_xhi[NS * IND];       // x hi bf16, [M][K]
__device__ __nv_bfloat16  g_xlo[NS * IND];       // x lo bf16
__device__ __nv_bfloat16  g_bhi[DD * IND];       // W^T hi, [N][K]
__device__ __nv_bfloat16  g_blo[DD * IND];       // W^T lo
__device__ __nv_bfloat16  g_phi[PP * DD];        // proto hi bf16, [P][D]
__device__ __nv_bfloat16  g_plo[PP * DD];        // proto lo bf16
__device__ float          g_pnorm2[PP];
__device__ float          g_pnorm_inv[PP];
__device__ float          g_pp_part[PP];
__device__ unsigned int   g_minBits[PP];
__device__ float          g_pz_sum;
__device__ float          g_cl_sum;
__device__ int            g_num_cnt;
__device__ int            g_done;                // reduction-block counter

__device__ __forceinline__ float warpSum(float v) {
#pragma unroll
    for (int o = 16; o; o >>= 1) v += __shfl_xor_sync(0xffffffffu, v, o);
    return v;
}

__device__ __forceinline__ uint32_t smem_u32(const void* p) {
    uint32_t a;
    asm("{ .reg .u64 t; cvta.to.shared.u64 t, %1; cvt.u32.u64 %0, t; }"
        : "=r"(a) : "l"(p));
    return a;
}

__device__ __forceinline__ void cp16(uint32_t sdst, const void* gsrc) {
    asm volatile("cp.async.cg.shared.global [%0], [%1], 16;"
                 :: "r"(sdst), "l"(gsrc) : "memory");
}

// m16n8k16 row.col f32.bf16.bf16.f32
__device__ __forceinline__ void mma16816(float (&d)[4], const uint32_t (&a)[4],
                                         const uint32_t (&b)[2]) {
    asm volatile(
        "mma.sync.aligned.m16n8k16.row.col.f32.bf16.bf16.f32 "
        "{%0,%1,%2,%3}, {%4,%5,%6,%7}, {%8,%9}, {%0,%1,%2,%3};"
        : "+f"(d[0]), "+f"(d[1]), "+f"(d[2]), "+f"(d[3])
        : "r"(a[0]), "r"(a[1]), "r"(a[2]), "r"(a[3]),
          "r"(b[0]), "r"(b[1]));
}

__device__ __forceinline__ void ldmx4(uint32_t (&r)[4], uint32_t addr) {
    asm volatile("ldmatrix.sync.aligned.m8n8.x4.shared.b16 {%0,%1,%2,%3}, [%4];"
                 : "=r"(r[0]), "=r"(r[1]), "=r"(r[2]), "=r"(r[3]) : "r"(addr));
}

__device__ __forceinline__ uint32_t bfpack(float a, float b) {
    const __nv_bfloat16 ha = __float2bfloat16_rn(a);
    const __nv_bfloat16 hb = __float2bfloat16_rn(b);
    return ((uint32_t)__bfloat16_as_ushort(hb) << 16) | __bfloat16_as_ushort(ha);
}

// GEMM smem layout (bf16, padded stride 72 bf16 = 144 B), CTA tile 128x64
#define ASTR     72
#define OFF_AHI  0
#define OFF_ALO  18432            // 128*72*2
#define OFF_BHI  36864
#define OFF_BLO  46080            // +64*72*2
#define GBUF     55296
#define SMEM_GEMM (2 * GBUF + 512)   // + zn2s[128]

#define NPROTO   PP                       // 64 proto blocks
#define NCONVW   ((IND / 32) * (DD / 32)) // 192 convW blocks
#define NCONVX   (NS * IND / 4 / 256)     // 3072 convX blocks
#define NPREP    (NPROTO + NCONVW + NCONVX)
#define NRED     (NS / 8)                 // 512 reduction blocks in k_tokens

// ---------------------------------------------------------------------------
// K_prep (mega): [0,64) proto norms + pp partials + proto hi/lo (slow, FIRST);
//                [64,256) W hi/lo split + transpose;
//                [256,3328) x hi/lo split + init/zero of accumulators.
// ---------------------------------------------------------------------------
__global__ __launch_bounds__(256)
void k_prep(const float* __restrict__ proto, const float* __restrict__ W,
            const float* __restrict__ X) {
    const int bid = blockIdx.x;
    const int t   = threadIdx.x;

    if (bid < NPROTO) {
        const int i = bid;
        __shared__ float pi[DD];
        __shared__ float red[8];
        __shared__ float ddist[PP];

        float v = proto[i * DD + t];
        pi[t] = v;
        const __nv_bfloat16 h = __float2bfloat16_rn(v);
        g_phi[i * DD + t] = h;
        g_plo[i * DD + t] = __float2bfloat16_rn(v - __bfloat162float(h));

        float nrm = warpSum(v * v);
        if ((t & 31) == 0) red[t >> 5] = nrm;
        __syncthreads();
        if (t == 0) {
            float s = 0.f;
#pragma unroll
            for (int w = 0; w < 8; w++) s += red[w];
            g_pnorm2[i]    = s;
            g_pnorm_inv[i] = 1.0f / fmaxf(sqrtf(s), 1e-8f);
        }
        __syncthreads();

        const int j = t >> 2;
        const int q = t & 3;
        const float* pj = proto + j * DD + q * 64;
        float s = 0.f;
#pragma unroll 8
        for (int d = 0; d < 64; d++) {
            float df = pi[q * 64 + d] - pj[d];
            s += df * df;
        }
        s += __shfl_down_sync(0xffffffffu, s, 1);
        s += __shfl_down_sync(0xffffffffu, s, 2);
        if (q == 0) ddist[j] = (j == i) ? 0.f : sqrtf(fmaxf(s, 0.f));
        __syncthreads();
        if (t == 0) {
            float acc = 0.f;
#pragma unroll
            for (int k = 0; k < PP; k++) acc += ddist[k];
            g_pp_part[i] = acc;
        }
        return;
    }

    if (bid < NPROTO + NCONVW) {
        // ---- convW: smem-tiled transpose + hi/lo split ----
        __shared__ float tile[32][33];
        const int bid2 = bid - NPROTO;
        const int k0 = (bid2 % (IND / 32)) * 32;
        const int n0 = (bid2 / (IND / 32)) * 32;
        const int tx = t & 31;
        const int ty = t >> 5;

#pragma unroll
        for (int r = 0; r < 4; r++) {
            const int k = ty + r * 8;
            tile[k][tx] = W[(size_t)(k0 + k) * DD + n0 + tx];
        }
        __syncthreads();

#pragma unroll
        for (int r = 0; r < 4; r++) {
            const int n = ty + r * 8;
            const float w = tile[tx][n];
            const __nv_bfloat16 h = __float2bfloat16_rn(w);
            const __nv_bfloat16 l = __float2bfloat16_rn(w - __bfloat162float(h));
            const size_t o = (size_t)(n0 + n) * IND + k0 + tx;
            g_bhi[o] = h;
            g_blo[o] = l;
        }
        return;
    }

    // ---- convX: x hi/lo split + init/zero ----
    {
        const int bid3 = bid - NPROTO - NCONVW;   // 0..3071
        if (bid3 == 0) {
            if (t < PP) g_minBits[t] = 0x7f7fffffu;
            if (t == 0) { g_pz_sum = 0.f; g_cl_sum = 0.f; g_num_cnt = 0; g_done = 0; }
        }
        if (bid3 < 1024)      g_dot[bid3 * 256 + t] = 0.f;
        else if (bid3 < 1040) g_zn2[(bid3 - 1024) * 256 + t] = 0.f;

        const int i = bid3 * 256 + t;             // float4 index
        const float4 v = ((const float4*)X)[i];
        const __nv_bfloat16 h0 = __float2bfloat16_rn(v.x);
        const __nv_bfloat16 h1 = __float2bfloat16_rn(v.y);
        const __nv_bfloat16 h2 = __float2bfloat16_rn(v.z);
        const __nv_bfloat16 h3 = __float2bfloat16_rn(v.w);
        const __nv_bfloat16 l0 = __float2bfloat16_rn(v.x - __bfloat162float(h0));
        const __nv_bfloat16 l1 = __float2bfloat16_rn(v.y - __bfloat162float(h1));
        const __nv_bfloat16 l2 = __float2bfloat16_rn(v.z - __bfloat162float(h2));
        const __nv_bfloat16 l3 = __float2bfloat16_rn(v.w - __bfloat162float(h3));
        const uint32_t hp0 = ((uint32_t)__bfloat16_as_ushort(h1) << 16) | __bfloat16_as_ushort(h0);
        const uint32_t hp1 = ((uint32_t)__bfloat16_as_ushort(h3) << 16) | __bfloat16_as_ushort(h2);
        const uint32_t lp0 = ((uint32_t)__bfloat16_as_ushort(l1) << 16) | __bfloat16_as_ushort(l0);
        const uint32_t lp1 = ((uint32_t)__bfloat16_as_ushort(l3) << 16) | __bfloat16_as_ushort(l2);
        ((uint2*)g_xhi)[i] = make_uint2(hp0, hp1);
        ((uint2*)g_xlo)[i] = make_uint2(lp0, lp1);
    }
}

// ---------------------------------------------------------------------------
// K_gemm_hmma: z = x@W+b (bf16x3 HMMA) + fused dot GEMM + zn2. (R12 verbatim)
// ---------------------------------------------------------------------------
__global__ __launch_bounds__(512, 1)
void k_gemm_hmma(const float* __restrict__ bias) {
    extern __shared__ __align__(128) char sm[];
    const uint32_t smb = smem_u32(sm);
    float* zn2s = (float*)(sm + 2 * GBUF);

    const int tid  = threadIdx.x;
    const int wid  = tid >> 5;
    const int lane = tid & 31;
    const int gid  = lane >> 2;
    const int tig  = lane & 3;
    const int m0   = blockIdx.x * 128;
    const int n0   = blockIdx.y * 64;
    const int wm   = (wid & 3) * 32;
    const int wn   = (wid >> 2) * 16;

    const int arow = lane & 15;
    const int acol = (lane >> 4) << 3;
    const int brow = (lane & 7) + ((lane >> 4) << 3);
    const int bcol = ((lane >> 3) & 1) << 3;

    auto stage = [&](int buf, int c) {
        const uint32_t bb = smb + buf * GBUF;
        const int k0 = c * 64;
#pragma unroll
        for (int i = 0; i < 2; i++) {
            const int idx = i * 512 + tid;
            const int r = idx >> 3, c8 = idx & 7;
            const size_t g = (size_t)(m0 + r) * IND + k0 + c8 * 8;
            const uint32_t d = bb + OFF_AHI + (uint32_t)(r * ASTR + c8 * 8) * 2;
            cp16(d,                       g_xhi + g);
            cp16(d + (OFF_ALO - OFF_AHI), g_xlo + g);
        }
        {
            const int r = tid >> 3, c8 = tid & 7;
            const size_t g = (size_t)(n0 + r) * IND + k0 + c8 * 8;
            const uint32_t d = bb + OFF_BHI + (uint32_t)(r * ASTR + c8 * 8) * 2;
            cp16(d,                       g_bhi + g);
            cp16(d + (OFF_BLO - OFF_BHI), g_blo + g);
        }
        asm volatile("cp.async.commit_group;" ::: "memory");
    };

    float acc[2][2][4];
#pragma unroll
    for (int mt = 0; mt < 2; mt++)
#pragma unroll
        for (int nt = 0; nt < 2; nt++)
#pragma unroll
            for (int q = 0; q < 4; q++) acc[mt][nt][q] = 0.f;

    stage(0, 0);

#pragma unroll 1
    for (int c = 0; c < 12; c++) {
        const int buf = c & 1;
        if (c < 11) {
            stage(buf ^ 1, c + 1);
            asm volatile("cp.async.wait_group 1;" ::: "memory");
        } else {
            asm volatile("cp.async.wait_group 0;" ::: "memory");
        }
        __syncthreads();

        const uint32_t bb = smb + buf * GBUF;
#pragma unroll
        for (int ks = 0; ks < 4; ks++) {
            const int kk = ks * 16;
            uint32_t Ahif[2][4], Alof[2][4];
#pragma unroll
            for (int mt = 0; mt < 2; mt++) {
                const uint32_t a = bb + OFF_AHI
                    + (uint32_t)((wm + mt * 16 + arow) * ASTR + kk + acol) * 2;
                ldmx4(Ahif[mt], a);
                ldmx4(Alof[mt], a + (OFF_ALO - OFF_AHI));
            }
            uint32_t Bhif[2][2], Blof[2][2];
            {
                const uint32_t a = bb + OFF_BHI
                    + (uint32_t)((wn + brow) * ASTR + kk + bcol) * 2;
                uint32_t rh[4], rl[4];
                ldmx4(rh, a);
                ldmx4(rl, a + (OFF_BLO - OFF_BHI));
                Bhif[0][0] = rh[0]; Bhif[0][1] = rh[1];
                Bhif[1][0] = rh[2]; Bhif[1][1] = rh[3];
                Blof[0][0] = rl[0]; Blof[0][1] = rl[1];
                Blof[1][0] = rl[2]; Blof[1][1] = rl[3];
            }
#pragma unroll
            for (int mt = 0; mt < 2; mt++)
#pragma unroll
                for (int nt = 0; nt < 2; nt++)
                    mma16816(acc[mt][nt], Ahif[mt], Bhif[nt]);
#pragma unroll
            for (int mt = 0; mt < 2; mt++)
#pragma unroll
                for (int nt = 0; nt < 2; nt++)
                    mma16816(acc[mt][nt], Ahif[mt], Blof[nt]);
#pragma unroll
            for (int mt = 0; mt < 2; mt++)
#pragma unroll
                for (int nt = 0; nt < 2; nt++)
                    mma16816(acc[mt][nt], Alof[mt], Bhif[nt]);
        }
        __syncthreads();
    }

    // ===== fused epilogue: z -> bf16 smem tile, zn2, dot GEMM =====
    if (tid < 128) zn2s[tid] = 0.f;

    {
        const int r = tid >> 3, c8 = tid & 7;
        const size_t g = (size_t)r * DD + n0 + c8 * 8;
        const uint32_t d = smb + OFF_BHI + (uint32_t)(r * ASTR + c8 * 8) * 2;
        cp16(d,                       g_phi + g);
        cp16(d + (OFF_BLO - OFF_BHI), g_plo + g);
        asm volatile("cp.async.commit_group;" ::: "memory");
    }
    __syncthreads();

#pragma unroll
    for (int nt = 0; nt < 2; nt++) {
        const int colg = n0 + wn + nt * 8 + tig * 2;
        const int coll = wn + nt * 8 + tig * 2;
        const float2 bv = *(const float2*)&bias[colg];
#pragma unroll
        for (int mt = 0; mt < 2; mt++) {
            const int rowl = wm + mt * 16 + gid;
            const float z0 = acc[mt][nt][0] + bv.x;
            const float z1 = acc[mt][nt][1] + bv.y;
            const float z2 = acc[mt][nt][2] + bv.x;
            const float z3 = acc[mt][nt][3] + bv.y;
            atomicAdd(&zn2s[rowl],     z0 * z0 + z1 * z1);
            atomicAdd(&zn2s[rowl + 8], z2 * z2 + z3 * z3);
            const __nv_bfloat16 h0 = __float2bfloat16_rn(z0);
            const __nv_bfloat16 h1 = __float2bfloat16_rn(z1);
            const __nv_bfloat16 h2 = __float2bfloat16_rn(z2);
            const __nv_bfloat16 h3 = __float2bfloat16_rn(z3);
            const uint32_t hp0 = ((uint32_t)__bfloat16_as_ushort(h1) << 16) | __bfloat16_as_ushort(h0);
            const uint32_t hp1 = ((uint32_t)__bfloat16_as_ushort(h3) << 16) | __bfloat16_as_ushort(h2);
            const uint32_t lp0 = bfpack(z0 - __bfloat162float(h0), z1 - __bfloat162float(h1));
            const uint32_t lp1 = bfpack(z2 - __bfloat162float(h2), z3 - __bfloat162float(h3));
            char* pa = sm + OFF_AHI + (uint32_t)(rowl * ASTR + coll) * 2;
            *(uint32_t*)(pa)                = hp0;
            *(uint32_t*)(pa + 8 * ASTR * 2) = hp1;
            char* pl = sm + OFF_ALO + (uint32_t)(rowl * ASTR + coll) * 2;
            *(uint32_t*)(pl)                = lp0;
            *(uint32_t*)(pl + 8 * ASTR * 2) = lp1;
        }
    }
    asm volatile("cp.async.wait_group 0;" ::: "memory");
    __syncthreads();

    float acc2[2][2][4];
#pragma unroll
    for (int mt = 0; mt < 2; mt++)
#pragma unroll
        for (int nt = 0; nt < 2; nt++)
#pragma unroll
            for (int q = 0; q < 4; q++) acc2[mt][nt][q] = 0.f;

#pragma unroll
    for (int ks = 0; ks < 4; ks++) {
        const int kk = ks * 16;
        uint32_t Ahif[2][4], Alof[2][4];
#pragma unroll
        for (int mt = 0; mt < 2; mt++) {
            const uint32_t a = smb + OFF_AHI
                + (uint32_t)((wm + mt * 16 + arow) * ASTR + kk + acol) * 2;
            ldmx4(Ahif[mt], a);
            ldmx4(Alof[mt], a + (OFF_ALO - OFF_AHI));
        }
        uint32_t Bhif[2][2], Blof[2][2];
        {
            const uint32_t a = smb + OFF_BHI
                + (uint32_t)((wn + brow) * ASTR + kk + bcol) * 2;
            uint32_t rh[4], rl[4];
            ldmx4(rh, a);
            ldmx4(rl, a + (OFF_BLO - OFF_BHI));
            Bhif[0][0] = rh[0]; Bhif[0][1] = rh[1];
            Bhif[1][0] = rh[2]; Bhif[1][1] = rh[3];
            Blof[0][0] = rl[0]; Blof[0][1] = rl[1];
            Blof[1][0] = rl[2]; Blof[1][1] = rl[3];
        }
#pragma unroll
        for (int mt = 0; mt < 2; mt++)
#pragma unroll
            for (int nt = 0; nt < 2; nt++)
                mma16816(acc2[mt][nt], Ahif[mt], Bhif[nt]);
#pragma unroll
        for (int mt = 0; mt < 2; mt++)
#pragma unroll
            for (int nt = 0; nt < 2; nt++)
                mma16816(acc2[mt][nt], Ahif[mt], Blof[nt]);
#pragma unroll
        for (int mt = 0; mt < 2; mt++)
#pragma unroll
            for (int nt = 0; nt < 2; nt++)
                mma16816(acc2[mt][nt], Alof[mt], Bhif[nt]);
    }

#pragma unroll
    for (int nt = 0; nt < 2; nt++) {
        const int p = wn + nt * 8 + tig * 2;
#pragma unroll
        for (int mt = 0; mt < 2; mt++) {
            const int row = m0 + wm + mt * 16 + gid;
            atomicAdd(&g_dot[(size_t)row * PP + p],           acc2[mt][nt][0]);
            atomicAdd(&g_dot[(size_t)row * PP + p + 1],       acc2[mt][nt][1]);
            atomicAdd(&g_dot[(size_t)(row + 8) * PP + p],     acc2[mt][nt][2]);
            atomicAdd(&g_dot[(size_t)(row + 8) * PP + p + 1], acc2[mt][nt][3]);
        }
    }
    __syncthreads();
    if (tid < 128) atomicAdd(&g_zn2[m0 + tid], zn2s[tid]);
}

// ---------------------------------------------------------------------------
// K_tokens (+post fused): grid = 16384 x 256, one sample per block.
// Blocks [0,512) first run the loss-reduction prologue for 8 samples each;
// the 512th finisher combines the scalar loss. ALL blocks then stream token
// writes, computing cos inline from g_dot/g_zn2 (warp-uniform loads; rz
// hoisted per block since n = blockIdx >> 2 is constant per block).
// ---------------------------------------------------------------------------
__global__ __launch_bounds__(256)
void k_tokens(const long long* __restrict__ labels,
              const float* __restrict__ proto,
              float* __restrict__ out, int loss_idx) {
    const int tid = threadIdx.x;
    const int b   = blockIdx.x;

    if (b < NRED) {
        // ---- reduction prologue (k_post body, sans g_cos write) ----
        __shared__ unsigned int bmin[PP];
        __shared__ float s_pz, s_cl;
        __shared__ int   s_cnt;

        const int s  = tid >> 5;
        const int pg = tid & 31;
        const int p0 = pg * 2;
        const int n  = b * 8 + s;

        if (tid < PP) bmin[tid] = 0x7f7fffffu;
        if (tid == 0) { s_pz = 0.f; s_cl = 0.f; s_cnt = 0; }
        __syncthreads();

        const float zn2r = g_zn2[n];
        const float rzr  = 1.0f / fmaxf(sqrtf(zn2r), 1e-8f);
        const float2 dt  = *(const float2*)&g_dot[(size_t)n * PP + p0];
        const float2 pinv = __ldg((const float2*)&g_pnorm_inv[p0]);
        const float2 pn2  = __ldg((const float2*)&g_pnorm2[p0]);

        const float cos0 = dt.x * rzr * pinv.x;
        const float cos1 = dt.y * rzr * pinv.y;
        const float dst0 = sqrtf(fmaxf(zn2r + pn2.x - 2.0f * dt.x, 0.f));
        const float dst1 = sqrtf(fmaxf(zn2r + pn2.y - 2.0f * dt.y, 0.f));

        atomicMin(&bmin[p0],     __float_as_uint(dst0));
        atomicMin(&bmin[p0 + 1], __float_as_uint(dst1));

        float minD = fminf(dst0, dst1);
        const float mx = fmaxf(cos0, cos1);
        const bool pos = (pg < 16);
        float mp = pos ? mx : -FLT_MAX;
        float mn = pos ? -FLT_MAX : mx;
        int cnt = (cos0 > 0.5f) + (cos1 > 0.5f);
#pragma unroll
        for (int o = 16; o; o >>= 1) {
            minD = fminf(minD, __shfl_xor_sync(0xffffffffu, minD, o));
            mp   = fmaxf(mp,   __shfl_xor_sync(0xffffffffu, mp,   o));
            mn   = fmaxf(mn,   __shfl_xor_sync(0xffffffffu, mn,   o));
            cnt += __shfl_xor_sync(0xffffffffu, cnt, o);
        }
        if (pg == 0) {
            const long long lb = labels[n];
            atomicAdd(&s_pz, minD);
            atomicAdd(&s_cl, (lb == 1) ? (1.0f - mp) : (1.0f - mn));
            if (cnt > PP / 4) atomicAdd(&s_cnt, 1);
        }
        __syncthreads();

        if (tid == 0) {
            atomicAdd(&g_pz_sum, s_pz);
            atomicAdd(&g_cl_sum, s_cl);
            if (s_cnt) atomicAdd(&g_num_cnt, s_cnt);
        }
        if (tid < PP) atomicMin(&g_minBits[tid], bmin[tid]);
        __threadfence();
        __syncthreads();

        if (tid == 0) {
            const int old = atomicAdd(&g_done, 1);
            if (old == NRED - 1) {
                // last reduction block: combine scalar loss (atomic reads
                // see latest L2 state)
                float zp = 0.f, pps = 0.f;
#pragma unroll
                for (int k = 0; k < PP; k++) {
                    zp  += __uint_as_float(atomicMin(&g_minBits[k], 0xffffffffu));
                    pps += g_pp_part[k];   // written 2 launches ago, L1 fresh
                }
                const float l_pz = atomicAdd(&g_pz_sum, 0.f);
                const float l_cl = atomicAdd(&g_cl_sum, 0.f);
                const int   l_nm = atomicAdd(&g_num_cnt, 0);
                out[loss_idx] = zp / (float)PP
                              + l_pz / (float)NS
                              + pps / (float)(PP * (PP - 1))
                              + (float)l_nm
                              + 2.0f * (l_cl / (float)NS);
            }
        }
    }

    // ---- token write phase (all blocks): n constant per block ----
    const int base = b * 1024;
    const int n    = b >> 2;
    const float zn2 = g_zn2[n];
    const float rz  = 1.0f / fmaxf(sqrtf(zn2), 1e-8f);
    const float4* proto4 = (const float4*)proto;
    float4* out4 = (float4*)out;
#pragma unroll
    for (int j = 0; j < 4; j++) {
        const int idx = base + j * 256 + tid;
        const int d4  = idx & 63;
        const int p   = (idx >> 6) & 63;
        const float c = __ldg(&g_dot[n * PP + p]) * rz * __ldg(&g_pnorm_inv[p]);
        const float4 pr = __ldg(proto4 + p * 64 + d4);
        out4[idx] = make_float4(c * pr.x, c * pr.y, c * pr.z, c * pr.w);
    }
}

// ---------------------------------------------------------------------------
// kernel_launch — 3 launches total
// ---------------------------------------------------------------------------
extern "C" void kernel_launch(void* const* d_in, const int* in_sizes, int n_in,
                              void* d_out, int out_size) {
    const float*     x      = nullptr;
    const long long* labels = nullptr;
    const float*     W      = nullptr;
    const float*     b      = nullptr;
    const float*     proto  = nullptr;
    for (int i = 0; i < n_in; i++) {
        switch (in_sizes[i]) {
            case NS * IND: x      = (const float*)d_in[i];     break;
            case NS:       labels = (const long long*)d_in[i]; break;
            case IND * DD: W      = (const float*)d_in[i];     break;
            case DD:       b      = (const float*)d_in[i];     break;
            case PP * DD:  proto  = (const float*)d_in[i];     break;
        }
    }
    if (!x || !labels || !W || !b || !proto) {
        x      = (const float*)d_in[0];
        labels = (const long long*)d_in[1];
        W      = (const float*)d_in[2];
        b      = (const float*)d_in[3];
        proto  = (const float*)d_in[4];
    }
    float* out = (float*)d_out;

    cudaFuncSetAttribute(k_gemm_hmma, cudaFuncAttributeMaxDynamicSharedMemorySize,
                         SMEM_GEMM);

    k_prep     <<<NPREP, 256>>>(proto, W, x);                        // 1
    k_gemm_hmma<<<dim3(NS / 128, DD / 64), 512, SMEM_GEMM>>>(b);     // 2
    k_tokens   <<<NS * PP * DD / 4 / 1024, 256>>>(labels, proto,     // 3
                                                  out, out_size - 1);
}